// round 16
// baseline (speedup 1.0000x reference)
#include <cuda_runtime.h>
#include <cuda_fp16.h>
#include <cstdint>

#define VOCAB 32000
#define EMB   256
#define UNITS 1024
#define BATCH 64
#define TLEN  512
#define N3    3072

#define GRID  128
#define TPB   512

// -------------------- device globals (no allocation allowed) ---------------
__device__ float g_xproj[(size_t)BATCH * TLEN * N3];            // [B*T, 3U]
__device__ __align__(16) __half g_hx[BATCH * UNITS];            // h  (fp16)
__device__ __align__(16) __half g_rhx[BATCH * UNITS];           // r*h (fp16)
__device__ unsigned g_count = 0;

// -------------------- helpers ----------------------------------------------
__device__ __forceinline__ uint32_t pack_h2(float lo, float hi) {
    __half2 h = __floats2half2_rn(lo, hi);
    return *(uint32_t*)&h;
}

__device__ __forceinline__ uint32_t s2u(const void* p) {
    uint32_t a;
    asm("{ .reg .u64 t; cvta.to.shared.u64 t, %1; cvt.u32.u64 %0, t; }"
        : "=r"(a) : "l"(p));
    return a;
}

__device__ __forceinline__ void cp_async16(uint32_t saddr, const void* gaddr) {
    asm volatile("cp.async.cg.shared.global [%0], [%1], 16;"
                 :: "r"(saddr), "l"(gaddr));
}
#define CP_COMMIT() asm volatile("cp.async.commit_group;")
#define CP_WAIT0()  asm volatile("cp.async.wait_group 0;")
#define CP_WAIT1()  asm volatile("cp.async.wait_group 1;")

#define MMA_F16(d0,d1,d2,d3,a0,a1,a2,a3,b0,b1)                                \
    asm volatile(                                                             \
        "mma.sync.aligned.m16n8k16.row.col.f32.f16.f16.f32 "                  \
        "{%0,%1,%2,%3},{%4,%5,%6,%7},{%8,%9},{%0,%1,%2,%3};"                  \
        : "+f"(d0), "+f"(d1), "+f"(d2), "+f"(d3)                              \
        : "r"(a0), "r"(a1), "r"(a2), "r"(a3), "r"(b0), "r"(b1))

#define CLUSTER_SYNC() do {                                                   \
    asm volatile("barrier.cluster.arrive.aligned;" ::: "memory");             \
    asm volatile("barrier.cluster.wait.aligned;"   ::: "memory");             \
} while (0)

__device__ __forceinline__ float dsmem_ld(uint32_t saddr, uint32_t rank) {
    uint32_t ra;
    asm("mapa.shared::cluster.u32 %0, %1, %2;" : "=r"(ra) : "r"(saddr), "r"(rank));
    float v;
    asm volatile("ld.shared::cluster.f32 %0, [%1];" : "=f"(v) : "r"(ra));
    return v;
}

// -------------------- grid barrier: monotonic release/acquire --------------
__device__ __forceinline__ void grid_barrier(unsigned target)
{
    __syncthreads();
    if (threadIdx.x == 0) {
        unsigned* cnt = &g_count;
        asm volatile("red.release.gpu.global.add.u32 [%0], %1;"
                     :: "l"(cnt), "r"(1u) : "memory");
        unsigned v;
        do {
            asm volatile("ld.acquire.gpu.global.u32 %0, [%1];"
                         : "=r"(v) : "l"(cnt) : "memory");
        } while (v < target);
    }
    __syncthreads();
}

// ---------------------------------------------------------------------------
// Kernel 1: xproj = gather(emb_table, x) @ kernel + bias — fp16 mma.sync
// (m16n8k16, fp32 accumulate). Staging identical to verified R11 pipeline;
// B fragment read FIXED to the [k][n] staged layout (R15 bug: indexed [n][k]).
// Resets g_count for replay determinism.
// ---------------------------------------------------------------------------
#define XKC   16
#define XNCH  (EMB / XKC)
#define ASTR  20
#define BSTR  136

__global__ __launch_bounds__(256) void xproj_f16(
    const int* __restrict__ x,
    const float* __restrict__ emb_table,
    const float* __restrict__ kernelW,
    const float* __restrict__ bias)
{
    if (blockIdx.x == 0 && blockIdx.y == 0 && threadIdx.x == 0)
        g_count = 0;

    __shared__ __align__(16) float As[2][128 * ASTR];
    __shared__ __align__(16) float Bs[2][XKC * BSTR];

    const int tid  = threadIdx.x;
    const int wid  = tid >> 5;
    const int lane = tid & 31;
    const int gID  = lane >> 2;
    const int tig  = lane & 3;
    const int wm   = wid & 1;
    const int wn   = wid >> 1;

    const int m0 = blockIdx.y * 128;
    const int n0 = blockIdx.x * 128;

    const int arow = tid & 127;
    const int ahalf = tid >> 7;
    const int token = x[m0 + arow];
    const float* aptr = emb_table + (size_t)token * EMB;
    const uint32_t a_s0 = s2u(&As[0][arow * ASTR + ahalf * 8]);
    const int abuf_delta = (int)(s2u(&As[1][0]) - s2u(&As[0][0]));

    const int bkrow = tid >> 4;
    const int bseg  = tid & 15;
    const uint32_t b_s0 = s2u(&Bs[0][bkrow * BSTR + bseg * 8]);
    const int bbuf_delta = (int)(s2u(&Bs[1][0]) - s2u(&Bs[0][0]));

    float acc[4][4][4];
#pragma unroll
    for (int mi = 0; mi < 4; mi++)
#pragma unroll
        for (int ni = 0; ni < 4; ni++)
#pragma unroll
            for (int c = 0; c < 4; c++) acc[mi][ni][c] = 0.f;

    {
        const float* ag = aptr + ahalf * 8;
        cp_async16(a_s0,      ag);
        cp_async16(a_s0 + 16, ag + 4);
        const float* bg = kernelW + (size_t)bkrow * N3 + n0 + bseg * 8;
        cp_async16(b_s0,      bg);
        cp_async16(b_s0 + 16, bg + 4);
        CP_COMMIT();
    }

    const int kb0 = 2 * tig;   // fragment k-offset within chunk (0,2,4,6)

    for (int kc = 0; kc < XNCH; kc++) {
        const int buf = kc & 1;
        if (kc + 1 < XNCH) {
            const int nb = (kc + 1) & 1;
            const float* ag = aptr + (kc + 1) * XKC + ahalf * 8;
            cp_async16(a_s0 + nb * abuf_delta,      ag);
            cp_async16(a_s0 + nb * abuf_delta + 16, ag + 4);
            const float* bg = kernelW + (size_t)((kc + 1) * XKC + bkrow) * N3 + n0 + bseg * 8;
            cp_async16(b_s0 + nb * bbuf_delta,      bg);
            cp_async16(b_s0 + nb * bbuf_delta + 16, bg + 4);
            CP_COMMIT();
            CP_WAIT1();
        } else {
            CP_WAIT0();
        }
        __syncthreads();

        const float* Ab = As[buf];
        const float* Bb = Bs[buf];

        uint32_t af[4][4], bf[4][2];
#pragma unroll
        for (int mi = 0; mi < 4; mi++) {
            const int mr = wm * 64 + mi * 16;
            float2 v0 = *(const float2*)&Ab[(mr + gID    ) * ASTR + kb0];
            float2 v1 = *(const float2*)&Ab[(mr + gID + 8) * ASTR + kb0];
            float2 v2 = *(const float2*)&Ab[(mr + gID    ) * ASTR + kb0 + 8];
            float2 v3 = *(const float2*)&Ab[(mr + gID + 8) * ASTR + kb0 + 8];
            af[mi][0] = pack_h2(v0.x, v0.y);
            af[mi][1] = pack_h2(v1.x, v1.y);
            af[mi][2] = pack_h2(v2.x, v2.y);
            af[mi][3] = pack_h2(v3.x, v3.y);
        }
#pragma unroll
        for (int ni = 0; ni < 4; ni++) {
            const int n = wn * 32 + ni * 8 + gID;
            // Bs layout is [k][n] (row stride BSTR): pack B[kb0][n],B[kb0+1][n]
            float b00 = Bb[(kb0    ) * BSTR + n];
            float b01 = Bb[(kb0 + 1) * BSTR + n];
            float b10 = Bb[(kb0 + 8) * BSTR + n];
            float b11 = Bb[(kb0 + 9) * BSTR + n];
            bf[ni][0] = pack_h2(b00, b01);
            bf[ni][1] = pack_h2(b10, b11);
        }
#pragma unroll
        for (int mi = 0; mi < 4; mi++)
#pragma unroll
            for (int ni = 0; ni < 4; ni++)
                MMA_F16(acc[mi][ni][0], acc[mi][ni][1],
                        acc[mi][ni][2], acc[mi][ni][3],
                        af[mi][0], af[mi][1], af[mi][2], af[mi][3],
                        bf[ni][0], bf[ni][1]);

        __syncthreads();
    }

#pragma unroll
    for (int mi = 0; mi < 4; mi++) {
#pragma unroll
        for (int ni = 0; ni < 4; ni++) {
            const int row = m0 + wm * 64 + mi * 16 + gID;
            const int col = n0 + wn * 32 + ni * 8 + 2 * tig;
            const float bz0 = bias[col], bz1 = bias[col + 1];
            float2 v0 = make_float2(acc[mi][ni][0] + bz0, acc[mi][ni][1] + bz1);
            float2 v1 = make_float2(acc[mi][ni][2] + bz0, acc[mi][ni][3] + bz1);
            *(float2*)&g_xproj[(size_t)row * N3 + col]       = v0;
            *(float2*)&g_xproj[(size_t)(row + 8) * N3 + col] = v1;
        }
    }
}

// ---------------------------------------------------------------------------
// Kernel 2: persistent GRU scan — cluster-2 split-K, fp16 MMA, 2-CHUNK
// pipelined staging. R14-VERBATIM (verified at 5096us).
// SMEM (uint32/float units):
//   ws   [48][260]    @ 0      Wz(0-15)/Wr(16-31)/Wh(32-47) cols, fp16 pairs
//   stg  [2][64][132] @ 12480  staged h/rh half-K slice, 2 chunks of 256 halfs
//   pacc (alias stg)  @ 12480  16x528 (A) / 16x272 (B), fp32
//   redA [64][33]     @ 29376
//   redB [64][17]     @ 31488
// total 32576 units = 130,304 B
// ---------------------------------------------------------------------------
#define SM_WS   0
#define SM_STG  12480
#define CHUNKU  8448       // 64 * 132 u32 per chunk buffer
#define SM_PACC 12480
#define SM_REDA 29376
#define SM_REDB 31488
#define SMEM_FLOATS 32576

__global__ void __launch_bounds__(TPB, 1) __cluster_dims__(2, 1, 1)
gru_scan(const float* __restrict__ hidden,
         const float* __restrict__ rk,
         float* __restrict__ out)
{
    extern __shared__ float sm[];
    uint32_t* smu = (uint32_t*)sm;
    float* pacc = sm + SM_PACC;
    float* redA = sm + SM_REDA;
    float* redB = sm + SM_REDB;

    const int tid   = threadIdx.x;
    const int cta   = blockIdx.x;
    const int crank = cta & 1;        // cluster rank (k-half owner)
    const int cg    = cta >> 1;       // column group 0..63
    const uint32_t peer = crank ^ 1;

    const int wid  = tid >> 5;
    const int lane = tid & 31;
    const int gID  = lane >> 2;
    const int tig  = lane & 3;
    const int mg   = wid & 3;         // m-group: rows [mg*16, mg*16+16)
    const int ksl  = wid >> 2;        // k-slice 0..3
    const int r0   = mg * 16 + gID;

    // gate/update mapping: 32 rows x 16 cols per CTA
    const int grow = crank * 32 + (tid >> 4);
    const int gcol = cg * 16 + (tid & 15);
    const int lcol = tid & 15;

    // reduction mapping (all 64 rows for peer)
    const int rrow = tid >> 3;
    const int rc4  = (tid & 7) * 4;
    const int rc2  = (tid & 7) * 2;
    const int rmgr = rrow >> 4;
    const int rlr  = rrow & 15;

    const int koff = crank * 512;     // k base (half units)

    // ---- load weight slice as fp16 pairs (16 cols x 3 gates x 256 pairs) ----
    for (int idx = tid; idx < 48 * 256; idx += TPB) {
        const int r  = idx >> 8;                 // ws col-row 0..47
        const int kp = idx & 255;                // k-pair 0..255
        const int col = (r >> 4) * UNITS + cg * 16 + (r & 15);
        const float w0 = rk[(size_t)(koff + 2 * kp    ) * N3 + col];
        const float w1 = rk[(size_t)(koff + 2 * kp + 1) * N3 + col];
        smu[SM_WS + r * 260 + kp] = pack_h2(w0, w1);
    }

    // ---- init g_hx (fp16 of hidden) + register h ----
    float hreg;
    {
        int gidx = cta * TPB + tid;              // 128*512 = 65536 exactly
        g_hx[gidx] = __float2half_rn(hidden[gidx]);
        hreg = hidden[grow * UNITS + gcol];
    }
    unsigned bseq = 0;
    grid_barrier(++bseq * GRID);

    // staging: per chunk, 4 x 16B per thread; chunk = 256 halfs/row = 512B/row
    int st_r[4], st_c[4];
    uint32_t st_s[4];
#pragma unroll
    for (int i = 0; i < 4; i++) {
        int flat = i * TPB + tid;               // 0..2047
        st_r[i] = flat >> 5;                    // row 0..63
        st_c[i] = flat & 31;                    // 16B slot 0..31
        st_s[i] = s2u(&smu[SM_STG + st_r[i] * 132 + st_c[i] * 4]);
    }

    const uint32_t* wsz0 = &smu[SM_WS + (gID     ) * 260];
    const uint32_t* wsz1 = &smu[SM_WS + (gID +  8) * 260];
    const uint32_t* wsr0 = &smu[SM_WS + (gID + 16) * 260];
    const uint32_t* wsr1 = &smu[SM_WS + (gID + 24) * 260];
    const uint32_t* wsh0 = &smu[SM_WS + (gID + 32) * 260];
    const uint32_t* wsh1 = &smu[SM_WS + (gID + 40) * 260];
    const int fcol = ksl * 8 + tig;              // frag pair-col within k-iter

    float zreg = 0.f;

    for (int t = 0; t < TLEN; t++) {
        const size_t xb = ((size_t)(grow * TLEN + t)) * N3 + gcol;
        const float xz = __ldcg(&g_xproj[xb]);
        const float xr = __ldcg(&g_xproj[xb + UNITS]);
        const float xh = __ldcg(&g_xproj[xb + 2 * UNITS]);

        // =================== Phase A: zr_partial = h @ [Wz|Wr] (half-K) ======
        {
            const char* src = (const char*)g_hx;

            float az0[4], az1[4], ar0[4], ar1[4];
#pragma unroll
            for (int c = 0; c < 4; c++) { az0[c]=0.f; az1[c]=0.f; ar0[c]=0.f; ar1[c]=0.f; }

            // commit both chunks up-front (chunk 0 first -> completes first)
#pragma unroll
            for (int cchunk = 0; cchunk < 2; cchunk++) {
#pragma unroll
                for (int i = 0; i < 4; i++)
                    cp_async16(st_s[i] + cchunk * (CHUNKU * 4),
                               src + ((size_t)(st_r[i] * UNITS + koff)) * 2
                                   + cchunk * 512 + st_c[i] * 16);
                CP_COMMIT();
            }

            CP_WAIT1();
            __syncthreads();
#pragma unroll
            for (int kc = 0; kc < 4; kc++) {
                const int kw = kc * 32 + fcol;           // weight index (full)
                const uint32_t* hb = &smu[SM_STG];
                uint32_t a0 = hb[(r0    ) * 132 + kw];
                uint32_t a1 = hb[(r0 + 8) * 132 + kw];
                uint32_t a2 = hb[(r0    ) * 132 + kw + 4];
                uint32_t a3 = hb[(r0 + 8) * 132 + kw + 4];
                MMA_F16(az0[0], az0[1], az0[2], az0[3], a0, a1, a2, a3, wsz0[kw], wsz0[kw + 4]);
                MMA_F16(az1[0], az1[1], az1[2], az1[3], a0, a1, a2, a3, wsz1[kw], wsz1[kw + 4]);
                MMA_F16(ar0[0], ar0[1], ar0[2], ar0[3], a0, a1, a2, a3, wsr0[kw], wsr0[kw + 4]);
                MMA_F16(ar1[0], ar1[1], ar1[2], ar1[3], a0, a1, a2, a3, wsr1[kw], wsr1[kw + 4]);
            }
            CP_WAIT0();
            __syncthreads();
#pragma unroll
            for (int kc = 0; kc < 4; kc++) {
                const int kwl = kc * 32 + fcol;          // local index in chunk1
                const int kw  = 128 + kwl;               // weight index (full)
                const uint32_t* hb = &smu[SM_STG + CHUNKU];
                uint32_t a0 = hb[(r0    ) * 132 + kwl];
                uint32_t a1 = hb[(r0 + 8) * 132 + kwl];
                uint32_t a2 = hb[(r0    ) * 132 + kwl + 4];
                uint32_t a3 = hb[(r0 + 8) * 132 + kwl + 4];
                MMA_F16(az0[0], az0[1], az0[2], az0[3], a0, a1, a2, a3, wsz0[kw], wsz0[kw + 4]);
                MMA_F16(az1[0], az1[1], az1[2], az1[3], a0, a1, a2, a3, wsz1[kw], wsz1[kw + 4]);
                MMA_F16(ar0[0], ar0[1], ar0[2], ar0[3], a0, a1, a2, a3, wsr0[kw], wsr0[kw + 4]);
                MMA_F16(ar1[0], ar1[1], ar1[2], ar1[3], a0, a1, a2, a3, wsr1[kw], wsr1[kw + 4]);
            }

            __syncthreads();   // all reads of stage done before pacc alias

            // warp partials: C[16x32], row stride 33
            float* pw = pacc + wid * 528;
            pw[(gID    ) * 33 +  0 + 2 * tig    ] = az0[0];
            pw[(gID    ) * 33 +  0 + 2 * tig + 1] = az0[1];
            pw[(gID + 8) * 33 +  0 + 2 * tig    ] = az0[2];
            pw[(gID + 8) * 33 +  0 + 2 * tig + 1] = az0[3];
            pw[(gID    ) * 33 +  8 + 2 * tig    ] = az1[0];
            pw[(gID    ) * 33 +  8 + 2 * tig + 1] = az1[1];
            pw[(gID + 8) * 33 +  8 + 2 * tig    ] = az1[2];
            pw[(gID + 8) * 33 +  8 + 2 * tig + 1] = az1[3];
            pw[(gID    ) * 33 + 16 + 2 * tig    ] = ar0[0];
            pw[(gID    ) * 33 + 16 + 2 * tig + 1] = ar0[1];
            pw[(gID + 8) * 33 + 16 + 2 * tig    ] = ar0[2];
            pw[(gID + 8) * 33 + 16 + 2 * tig + 1] = ar0[3];
            pw[(gID    ) * 33 + 24 + 2 * tig    ] = ar1[0];
            pw[(gID    ) * 33 + 24 + 2 * tig + 1] = ar1[1];
            pw[(gID + 8) * 33 + 24 + 2 * tig    ] = ar1[2];
            pw[(gID + 8) * 33 + 24 + 2 * tig + 1] = ar1[3];
            __syncthreads();

            // reduce 4 k-slices -> redA[64][33]
            {
                float s0 = 0.f, s1 = 0.f, s2 = 0.f, s3 = 0.f;
#pragma unroll
                for (int s = 0; s < 4; s++) {
                    const float* p = pacc + (s * 4 + rmgr) * 528 + rlr * 33 + rc4;
                    s0 += p[0]; s1 += p[1]; s2 += p[2]; s3 += p[3];
                }
                float* rd = redA + rrow * 33 + rc4;
                rd[0] = s0; rd[1] = s1; rd[2] = s2; rd[3] = s3;
            }
            CLUSTER_SYNC();

            // gates: own + peer half-K partial (DSMEM)
            {
                const uint32_t zloc = s2u(&redA[grow * 33 + lcol]);
                const uint32_t rloc = s2u(&redA[grow * 33 + 16 + lcol]);
                float zp = sm[SM_REDA + grow * 33 + lcol]      + dsmem_ld(zloc, peer);
                float rp = sm[SM_REDA + grow * 33 + 16 + lcol] + dsmem_ld(rloc, peer);
                float z = 1.f / (1.f + __expf(-(xz + zp)));
                float r = 1.f / (1.f + __expf(-(xr + rp)));
                g_rhx[grow * UNITS + gcol] = __float2half_rn(r * hreg);
                zreg = z;
            }
        }
        grid_barrier(++bseq * GRID);

        // =================== Phase B: mh_partial = rh @ Wh (half-K) ==========
        {
            const char* src = (const char*)g_rhx;

            float ah0[4], ah1[4];
#pragma unroll
            for (int c = 0; c < 4; c++) { ah0[c] = 0.f; ah1[c] = 0.f; }

#pragma unroll
            for (int cchunk = 0; cchunk < 2; cchunk++) {
#pragma unroll
                for (int i = 0; i < 4; i++)
                    cp_async16(st_s[i] + cchunk * (CHUNKU * 4),
                               src + ((size_t)(st_r[i] * UNITS + koff)) * 2
                                   + cchunk * 512 + st_c[i] * 16);
                CP_COMMIT();
            }

            CP_WAIT1();
            __syncthreads();
#pragma unroll
            for (int kc = 0; kc < 4; kc++) {
                const int kw = kc * 32 + fcol;
                const uint32_t* hb = &smu[SM_STG];
                uint32_t a0 = hb[(r0    ) * 132 + kw];
                uint32_t a1 = hb[(r0 + 8) * 132 + kw];
                uint32_t a2 = hb[(r0    ) * 132 + kw + 4];
                uint32_t a3 = hb[(r0 + 8) * 132 + kw + 4];
                MMA_F16(ah0[0], ah0[1], ah0[2], ah0[3], a0, a1, a2, a3, wsh0[kw], wsh0[kw + 4]);
                MMA_F16(ah1[0], ah1[1], ah1[2], ah1[3], a0, a1, a2, a3, wsh1[kw], wsh1[kw + 4]);
            }
            CP_WAIT0();
            __syncthreads();
#pragma unroll
            for (int kc = 0; kc < 4; kc++) {
                const int kwl = kc * 32 + fcol;
                const int kw  = 128 + kwl;
                const uint32_t* hb = &smu[SM_STG + CHUNKU];
                uint32_t a0 = hb[(r0    ) * 132 + kwl];
                uint32_t a1 = hb[(r0 + 8) * 132 + kwl];
                uint32_t a2 = hb[(r0    ) * 132 + kwl + 4];
                uint32_t a3 = hb[(r0 + 8) * 132 + kwl + 4];
                MMA_F16(ah0[0], ah0[1], ah0[2], ah0[3], a0, a1, a2, a3, wsh0[kw], wsh0[kw + 4]);
                MMA_F16(ah1[0], ah1[1], ah1[2], ah1[3], a0, a1, a2, a3, wsh1[kw], wsh1[kw + 4]);
            }

            __syncthreads();

            // warp partials: C[16x16], row stride 17
            float* pw = pacc + wid * 272;
            pw[(gID    ) * 17 + 0 + 2 * tig    ] = ah0[0];
            pw[(gID    ) * 17 + 0 + 2 * tig + 1] = ah0[1];
            pw[(gID + 8) * 17 + 0 + 2 * tig    ] = ah0[2];
            pw[(gID + 8) * 17 + 0 + 2 * tig + 1] = ah0[3];
            pw[(gID    ) * 17 + 8 + 2 * tig    ] = ah1[0];
            pw[(gID    ) * 17 + 8 + 2 * tig + 1] = ah1[1];
            pw[(gID + 8) * 17 + 8 + 2 * tig    ] = ah1[2];
            pw[(gID + 8) * 17 + 8 + 2 * tig + 1] = ah1[3];
            __syncthreads();

            // reduce 4 k-slices -> redB[64][17]
            {
                float s0 = 0.f, s1 = 0.f;
#pragma unroll
                for (int s = 0; s < 4; s++) {
                    const float* p = pacc + (s * 4 + rmgr) * 272 + rlr * 17 + rc2;
                    s0 += p[0]; s1 += p[1];
                }
                float* rd = redB + rrow * 17 + rc2;
                rd[0] = s0; rd[1] = s1;
            }
            CLUSTER_SYNC();

            // h update: own + peer partial
            {
                const uint32_t hlocA = s2u(&redB[grow * 17 + lcol]);
                float mp = sm[SM_REDB + grow * 17 + lcol] + dsmem_ld(hlocA, peer);
                const float a = xh + mp;
                const float hh = 1.f - 2.f / (1.f + __expf(2.f * a));  // tanh(a)
                const float hn = zreg * hreg + (1.f - zreg) * hh;
                hreg = hn;
                g_hx[grow * UNITS + gcol] = __float2half_rn(hn);
                out[((size_t)(grow * TLEN + t)) * UNITS + gcol] = hn;
                if (t == TLEN - 1)
                    out[(size_t)BATCH * TLEN * UNITS + (size_t)grow * UNITS + gcol] = hn;
            }
        }
        grid_barrier(++bseq * GRID);
    }
}

// ---------------------------------------------------------------------------
extern "C" void kernel_launch(void* const* d_in, const int* in_sizes, int n_in,
                              void* d_out, int out_size)
{
    const int*   x      = (const int*)d_in[0];
    const float* hidden = (const float*)d_in[1];
    const float* emb    = (const float*)d_in[2];
    const float* kern   = (const float*)d_in[3];
    const float* rk     = (const float*)d_in[4];
    const float* bias   = (const float*)d_in[5];
    float* out = (float*)d_out;

    static bool attr_set = false;
    if (!attr_set) {
        cudaFuncSetAttribute(gru_scan, cudaFuncAttributeMaxDynamicSharedMemorySize,
                             SMEM_FLOATS * sizeof(float));
        attr_set = true;
    }

    // Node 1: projection GEMM (fp16 MMA, cp.async pipelined) + barrier reset
    xproj_f16<<<dim3(N3 / 128, (BATCH * TLEN) / 128), 256>>>(x, emb, kern, bias);

    // Node 2: persistent GRU scan (cluster-2 split-K, fp16, 2-chunk pipeline)
    gru_scan<<<GRID, TPB, SMEM_FLOATS * sizeof(float)>>>(hidden, rk, out);
}

// round 17
// speedup vs baseline: 1.0157x; 1.0157x over previous
#include <cuda_runtime.h>
#include <cuda_fp16.h>
#include <cstdint>

#define VOCAB 32000
#define EMB   256
#define UNITS 1024
#define BATCH 64
#define TLEN  512
#define N3    3072

#define GRID  128
#define TPB   512

// -------------------- device globals (no allocation allowed) ---------------
__device__ float g_xproj[(size_t)BATCH * TLEN * N3];            // [B*T, 3U]
__device__ __align__(16) __half g_hx[BATCH * UNITS];            // h  (fp16)
__device__ __align__(16) __half g_rhx[BATCH * UNITS];           // r*h (fp16)
__device__ unsigned g_count = 0;

// -------------------- helpers ----------------------------------------------
__device__ __forceinline__ uint32_t f2tf32(float x) {
    uint32_t r;
    asm("cvt.rna.tf32.f32 %0, %1;" : "=r"(r) : "f"(x));
    return r;
}

__device__ __forceinline__ uint32_t pack_h2(float lo, float hi) {
    __half2 h = __floats2half2_rn(lo, hi);
    return *(uint32_t*)&h;
}

__device__ __forceinline__ uint32_t s2u(const void* p) {
    uint32_t a;
    asm("{ .reg .u64 t; cvta.to.shared.u64 t, %1; cvt.u32.u64 %0, t; }"
        : "=r"(a) : "l"(p));
    return a;
}

__device__ __forceinline__ void cp_async16(uint32_t saddr, const void* gaddr) {
    asm volatile("cp.async.cg.shared.global [%0], [%1], 16;"
                 :: "r"(saddr), "l"(gaddr));
}
#define CP_COMMIT() asm volatile("cp.async.commit_group;")
#define CP_WAIT0()  asm volatile("cp.async.wait_group 0;")
#define CP_WAIT1()  asm volatile("cp.async.wait_group 1;")

#define MMA_TF32(d0,d1,d2,d3,a0,a1,a2,a3,b0,b1)                               \
    asm volatile(                                                             \
        "mma.sync.aligned.m16n8k8.row.col.f32.tf32.tf32.f32 "                 \
        "{%0,%1,%2,%3},{%4,%5,%6,%7},{%8,%9},{%0,%1,%2,%3};"                  \
        : "+f"(d0), "+f"(d1), "+f"(d2), "+f"(d3)                              \
        : "r"(a0), "r"(a1), "r"(a2), "r"(a3), "r"(b0), "r"(b1))

#define MMA_F16(d0,d1,d2,d3,a0,a1,a2,a3,b0,b1)                                \
    asm volatile(                                                             \
        "mma.sync.aligned.m16n8k16.row.col.f32.f16.f16.f32 "                  \
        "{%0,%1,%2,%3},{%4,%5,%6,%7},{%8,%9},{%0,%1,%2,%3};"                  \
        : "+f"(d0), "+f"(d1), "+f"(d2), "+f"(d3)                              \
        : "r"(a0), "r"(a1), "r"(a2), "r"(a3), "r"(b0), "r"(b1))

#define CLUSTER_SYNC() do {                                                   \
    asm volatile("barrier.cluster.arrive.aligned;" ::: "memory");             \
    asm volatile("barrier.cluster.wait.aligned;"   ::: "memory");             \
} while (0)

__device__ __forceinline__ float dsmem_ld(uint32_t saddr, uint32_t rank) {
    uint32_t ra;
    asm("mapa.shared::cluster.u32 %0, %1, %2;" : "=r"(ra) : "r"(saddr), "r"(rank));
    float v;
    asm volatile("ld.shared::cluster.f32 %0, [%1];" : "=f"(v) : "r"(ra));
    return v;
}

// -------------------- grid barrier: monotonic release/acquire --------------
__device__ __forceinline__ void grid_barrier(unsigned target)
{
    __syncthreads();
    if (threadIdx.x == 0) {
        unsigned* cnt = &g_count;
        asm volatile("red.release.gpu.global.add.u32 [%0], %1;"
                     :: "l"(cnt), "r"(1u) : "memory");
        unsigned v;
        do {
            asm volatile("ld.acquire.gpu.global.u32 %0, [%1];"
                         : "=r"(v) : "l"(cnt) : "memory");
        } while (v < target);
    }
    __syncthreads();
}

// ---------------------------------------------------------------------------
// Kernel 1: xproj = gather(emb_table, x) @ kernel + bias — tf32 mma.sync,
// cp.async double-buffered (R14-verbatim, verified 512us) + occupancy 2
// via __launch_bounds__(256, 2). Resets g_count for replay determinism.
// ---------------------------------------------------------------------------
#define XKC   16
#define XNCH  (EMB / XKC)
#define ASTR  20
#define BSTR  136

__global__ __launch_bounds__(256, 2) void xproj_tf32(
    const int* __restrict__ x,
    const float* __restrict__ emb_table,
    const float* __restrict__ kernelW,
    const float* __restrict__ bias)
{
    if (blockIdx.x == 0 && blockIdx.y == 0 && threadIdx.x == 0)
        g_count = 0;

    __shared__ __align__(16) float As[2][128 * ASTR];
    __shared__ __align__(16) float Bs[2][XKC * BSTR];

    const int tid  = threadIdx.x;
    const int wid  = tid >> 5;
    const int lane = tid & 31;
    const int gID  = lane >> 2;
    const int tig  = lane & 3;
    const int wm   = wid & 1;
    const int wn   = wid >> 1;

    const int m0 = blockIdx.y * 128;
    const int n0 = blockIdx.x * 128;

    const int arow = tid & 127;
    const int ahalf = tid >> 7;
    const int token = x[m0 + arow];
    const float* aptr = emb_table + (size_t)token * EMB;
    const uint32_t a_s0 = s2u(&As[0][arow * ASTR + ahalf * 8]);
    const int abuf_delta = (int)(s2u(&As[1][0]) - s2u(&As[0][0]));

    const int bkrow = tid >> 4;
    const int bseg  = tid & 15;
    const uint32_t b_s0 = s2u(&Bs[0][bkrow * BSTR + bseg * 8]);
    const int bbuf_delta = (int)(s2u(&Bs[1][0]) - s2u(&Bs[0][0]));

    float acc[4][4][4];
#pragma unroll
    for (int mi = 0; mi < 4; mi++)
#pragma unroll
        for (int ni = 0; ni < 4; ni++)
#pragma unroll
            for (int c = 0; c < 4; c++) acc[mi][ni][c] = 0.f;

    {
        const float* ag = aptr + ahalf * 8;
        cp_async16(a_s0,      ag);
        cp_async16(a_s0 + 16, ag + 4);
        const float* bg = kernelW + (size_t)bkrow * N3 + n0 + bseg * 8;
        cp_async16(b_s0,      bg);
        cp_async16(b_s0 + 16, bg + 4);
        CP_COMMIT();
    }

    for (int kc = 0; kc < XNCH; kc++) {
        const int buf = kc & 1;
        if (kc + 1 < XNCH) {
            const int nb = (kc + 1) & 1;
            const float* ag = aptr + (kc + 1) * XKC + ahalf * 8;
            cp_async16(a_s0 + nb * abuf_delta,      ag);
            cp_async16(a_s0 + nb * abuf_delta + 16, ag + 4);
            const float* bg = kernelW + (size_t)((kc + 1) * XKC + bkrow) * N3 + n0 + bseg * 8;
            cp_async16(b_s0 + nb * bbuf_delta,      bg);
            cp_async16(b_s0 + nb * bbuf_delta + 16, bg + 4);
            CP_COMMIT();
            CP_WAIT1();
        } else {
            CP_WAIT0();
        }
        __syncthreads();

        const float* Ab = As[buf];
        const float* Bb = Bs[buf];
#pragma unroll
        for (int kt = 0; kt < 2; kt++) {
            const int kb = kt * 8;
            uint32_t af[4][4], bf[4][2];
#pragma unroll
            for (int mi = 0; mi < 4; mi++) {
                const int mr = wm * 64 + mi * 16;
                af[mi][0] = f2tf32(Ab[(mr + gID    ) * ASTR + kb + tig]);
                af[mi][1] = f2tf32(Ab[(mr + gID + 8) * ASTR + kb + tig]);
                af[mi][2] = f2tf32(Ab[(mr + gID    ) * ASTR + kb + tig + 4]);
                af[mi][3] = f2tf32(Ab[(mr + gID + 8) * ASTR + kb + tig + 4]);
            }
#pragma unroll
            for (int ni = 0; ni < 4; ni++) {
                const int nb2 = wn * 32 + ni * 8 + gID;
                bf[ni][0] = f2tf32(Bb[(kb + tig    ) * BSTR + nb2]);
                bf[ni][1] = f2tf32(Bb[(kb + tig + 4) * BSTR + nb2]);
            }
#pragma unroll
            for (int mi = 0; mi < 4; mi++)
#pragma unroll
                for (int ni = 0; ni < 4; ni++)
                    MMA_TF32(acc[mi][ni][0], acc[mi][ni][1],
                             acc[mi][ni][2], acc[mi][ni][3],
                             af[mi][0], af[mi][1], af[mi][2], af[mi][3],
                             bf[ni][0], bf[ni][1]);
        }
        __syncthreads();
    }

#pragma unroll
    for (int mi = 0; mi < 4; mi++) {
#pragma unroll
        for (int ni = 0; ni < 4; ni++) {
            const int row = m0 + wm * 64 + mi * 16 + gID;
            const int col = n0 + wn * 32 + ni * 8 + 2 * tig;
            const float bz0 = bias[col], bz1 = bias[col + 1];
            float2 v0 = make_float2(acc[mi][ni][0] + bz0, acc[mi][ni][1] + bz1);
            float2 v1 = make_float2(acc[mi][ni][2] + bz0, acc[mi][ni][3] + bz1);
            *(float2*)&g_xproj[(size_t)row * N3 + col]       = v0;
            *(float2*)&g_xproj[(size_t)(row + 8) * N3 + col] = v1;
        }
    }
}

// ---------------------------------------------------------------------------
// Kernel 2: persistent GRU scan — cluster-2 split-K, fp16 MMA, 2-CHUNK
// pipelined staging. R14-VERBATIM (verified at 5096us).
// SMEM (uint32/float units):
//   ws   [48][260]    @ 0      Wz(0-15)/Wr(16-31)/Wh(32-47) cols, fp16 pairs
//   stg  [2][64][132] @ 12480  staged h/rh half-K slice, 2 chunks of 256 halfs
//   pacc (alias stg)  @ 12480  16x528 (A) / 16x272 (B), fp32
//   redA [64][33]     @ 29376
//   redB [64][17]     @ 31488
// total 32576 units = 130,304 B
// ---------------------------------------------------------------------------
#define SM_WS   0
#define SM_STG  12480
#define CHUNKU  8448       // 64 * 132 u32 per chunk buffer
#define SM_PACC 12480
#define SM_REDA 29376
#define SM_REDB 31488
#define SMEM_FLOATS 32576

__global__ void __launch_bounds__(TPB, 1) __cluster_dims__(2, 1, 1)
gru_scan(const float* __restrict__ hidden,
         const float* __restrict__ rk,
         float* __restrict__ out)
{
    extern __shared__ float sm[];
    uint32_t* smu = (uint32_t*)sm;
    float* pacc = sm + SM_PACC;
    float* redA = sm + SM_REDA;
    float* redB = sm + SM_REDB;

    const int tid   = threadIdx.x;
    const int cta   = blockIdx.x;
    const int crank = cta & 1;        // cluster rank (k-half owner)
    const int cg    = cta >> 1;       // column group 0..63
    const uint32_t peer = crank ^ 1;

    const int wid  = tid >> 5;
    const int lane = tid & 31;
    const int gID  = lane >> 2;
    const int tig  = lane & 3;
    const int mg   = wid & 3;         // m-group: rows [mg*16, mg*16+16)
    const int ksl  = wid >> 2;        // k-slice 0..3
    const int r0   = mg * 16 + gID;

    // gate/update mapping: 32 rows x 16 cols per CTA
    const int grow = crank * 32 + (tid >> 4);
    const int gcol = cg * 16 + (tid & 15);
    const int lcol = tid & 15;

    // reduction mapping (all 64 rows for peer)
    const int rrow = tid >> 3;
    const int rc4  = (tid & 7) * 4;
    const int rc2  = (tid & 7) * 2;
    const int rmgr = rrow >> 4;
    const int rlr  = rrow & 15;

    const int koff = crank * 512;     // k base (half units)

    // ---- load weight slice as fp16 pairs (16 cols x 3 gates x 256 pairs) ----
    for (int idx = tid; idx < 48 * 256; idx += TPB) {
        const int r  = idx >> 8;                 // ws col-row 0..47
        const int kp = idx & 255;                // k-pair 0..255
        const int col = (r >> 4) * UNITS + cg * 16 + (r & 15);
        const float w0 = rk[(size_t)(koff + 2 * kp    ) * N3 + col];
        const float w1 = rk[(size_t)(koff + 2 * kp + 1) * N3 + col];
        smu[SM_WS + r * 260 + kp] = pack_h2(w0, w1);
    }

    // ---- init g_hx (fp16 of hidden) + register h ----
    float hreg;
    {
        int gidx = cta * TPB + tid;              // 128*512 = 65536 exactly
        g_hx[gidx] = __float2half_rn(hidden[gidx]);
        hreg = hidden[grow * UNITS + gcol];
    }
    unsigned bseq = 0;
    grid_barrier(++bseq * GRID);

    // staging: per chunk, 4 x 16B per thread; chunk = 256 halfs/row = 512B/row
    int st_r[4], st_c[4];
    uint32_t st_s[4];
#pragma unroll
    for (int i = 0; i < 4; i++) {
        int flat = i * TPB + tid;               // 0..2047
        st_r[i] = flat >> 5;                    // row 0..63
        st_c[i] = flat & 31;                    // 16B slot 0..31
        st_s[i] = s2u(&smu[SM_STG + st_r[i] * 132 + st_c[i] * 4]);
    }

    const uint32_t* wsz0 = &smu[SM_WS + (gID     ) * 260];
    const uint32_t* wsz1 = &smu[SM_WS + (gID +  8) * 260];
    const uint32_t* wsr0 = &smu[SM_WS + (gID + 16) * 260];
    const uint32_t* wsr1 = &smu[SM_WS + (gID + 24) * 260];
    const uint32_t* wsh0 = &smu[SM_WS + (gID + 32) * 260];
    const uint32_t* wsh1 = &smu[SM_WS + (gID + 40) * 260];
    const int fcol = ksl * 8 + tig;              // frag pair-col within k-iter

    float zreg = 0.f;

    for (int t = 0; t < TLEN; t++) {
        const size_t xb = ((size_t)(grow * TLEN + t)) * N3 + gcol;
        const float xz = __ldcg(&g_xproj[xb]);
        const float xr = __ldcg(&g_xproj[xb + UNITS]);
        const float xh = __ldcg(&g_xproj[xb + 2 * UNITS]);

        // =================== Phase A: zr_partial = h @ [Wz|Wr] (half-K) ======
        {
            const char* src = (const char*)g_hx;

            float az0[4], az1[4], ar0[4], ar1[4];
#pragma unroll
            for (int c = 0; c < 4; c++) { az0[c]=0.f; az1[c]=0.f; ar0[c]=0.f; ar1[c]=0.f; }

            // commit both chunks up-front (chunk 0 first -> completes first)
#pragma unroll
            for (int cchunk = 0; cchunk < 2; cchunk++) {
#pragma unroll
                for (int i = 0; i < 4; i++)
                    cp_async16(st_s[i] + cchunk * (CHUNKU * 4),
                               src + ((size_t)(st_r[i] * UNITS + koff)) * 2
                                   + cchunk * 512 + st_c[i] * 16);
                CP_COMMIT();
            }

            CP_WAIT1();
            __syncthreads();
#pragma unroll
            for (int kc = 0; kc < 4; kc++) {
                const int kw = kc * 32 + fcol;           // weight index (full)
                const uint32_t* hb = &smu[SM_STG];
                uint32_t a0 = hb[(r0    ) * 132 + kw];
                uint32_t a1 = hb[(r0 + 8) * 132 + kw];
                uint32_t a2 = hb[(r0    ) * 132 + kw + 4];
                uint32_t a3 = hb[(r0 + 8) * 132 + kw + 4];
                MMA_F16(az0[0], az0[1], az0[2], az0[3], a0, a1, a2, a3, wsz0[kw], wsz0[kw + 4]);
                MMA_F16(az1[0], az1[1], az1[2], az1[3], a0, a1, a2, a3, wsz1[kw], wsz1[kw + 4]);
                MMA_F16(ar0[0], ar0[1], ar0[2], ar0[3], a0, a1, a2, a3, wsr0[kw], wsr0[kw + 4]);
                MMA_F16(ar1[0], ar1[1], ar1[2], ar1[3], a0, a1, a2, a3, wsr1[kw], wsr1[kw + 4]);
            }
            CP_WAIT0();
            __syncthreads();
#pragma unroll
            for (int kc = 0; kc < 4; kc++) {
                const int kwl = kc * 32 + fcol;          // local index in chunk1
                const int kw  = 128 + kwl;               // weight index (full)
                const uint32_t* hb = &smu[SM_STG + CHUNKU];
                uint32_t a0 = hb[(r0    ) * 132 + kwl];
                uint32_t a1 = hb[(r0 + 8) * 132 + kwl];
                uint32_t a2 = hb[(r0    ) * 132 + kwl + 4];
                uint32_t a3 = hb[(r0 + 8) * 132 + kwl + 4];
                MMA_F16(az0[0], az0[1], az0[2], az0[3], a0, a1, a2, a3, wsz0[kw], wsz0[kw + 4]);
                MMA_F16(az1[0], az1[1], az1[2], az1[3], a0, a1, a2, a3, wsz1[kw], wsz1[kw + 4]);
                MMA_F16(ar0[0], ar0[1], ar0[2], ar0[3], a0, a1, a2, a3, wsr0[kw], wsr0[kw + 4]);
                MMA_F16(ar1[0], ar1[1], ar1[2], ar1[3], a0, a1, a2, a3, wsr1[kw], wsr1[kw + 4]);
            }

            __syncthreads();   // all reads of stage done before pacc alias

            // warp partials: C[16x32], row stride 33
            float* pw = pacc + wid * 528;
            pw[(gID    ) * 33 +  0 + 2 * tig    ] = az0[0];
            pw[(gID    ) * 33 +  0 + 2 * tig + 1] = az0[1];
            pw[(gID + 8) * 33 +  0 + 2 * tig    ] = az0[2];
            pw[(gID + 8) * 33 +  0 + 2 * tig + 1] = az0[3];
            pw[(gID    ) * 33 +  8 + 2 * tig    ] = az1[0];
            pw[(gID    ) * 33 +  8 + 2 * tig + 1] = az1[1];
            pw[(gID + 8) * 33 +  8 + 2 * tig    ] = az1[2];
            pw[(gID + 8) * 33 +  8 + 2 * tig + 1] = az1[3];
            pw[(gID    ) * 33 + 16 + 2 * tig    ] = ar0[0];
            pw[(gID    ) * 33 + 16 + 2 * tig + 1] = ar0[1];
            pw[(gID + 8) * 33 + 16 + 2 * tig    ] = ar0[2];
            pw[(gID + 8) * 33 + 16 + 2 * tig + 1] = ar0[3];
            pw[(gID    ) * 33 + 24 + 2 * tig    ] = ar1[0];
            pw[(gID    ) * 33 + 24 + 2 * tig + 1] = ar1[1];
            pw[(gID + 8) * 33 + 24 + 2 * tig    ] = ar1[2];
            pw[(gID + 8) * 33 + 24 + 2 * tig + 1] = ar1[3];
            __syncthreads();

            // reduce 4 k-slices -> redA[64][33]
            {
                float s0 = 0.f, s1 = 0.f, s2 = 0.f, s3 = 0.f;
#pragma unroll
                for (int s = 0; s < 4; s++) {
                    const float* p = pacc + (s * 4 + rmgr) * 528 + rlr * 33 + rc4;
                    s0 += p[0]; s1 += p[1]; s2 += p[2]; s3 += p[3];
                }
                float* rd = redA + rrow * 33 + rc4;
                rd[0] = s0; rd[1] = s1; rd[2] = s2; rd[3] = s3;
            }
            CLUSTER_SYNC();

            // gates: own + peer half-K partial (DSMEM)
            {
                const uint32_t zloc = s2u(&redA[grow * 33 + lcol]);
                const uint32_t rloc = s2u(&redA[grow * 33 + 16 + lcol]);
                float zp = sm[SM_REDA + grow * 33 + lcol]      + dsmem_ld(zloc, peer);
                float rp = sm[SM_REDA + grow * 33 + 16 + lcol] + dsmem_ld(rloc, peer);
                float z = 1.f / (1.f + __expf(-(xz + zp)));
                float r = 1.f / (1.f + __expf(-(xr + rp)));
                g_rhx[grow * UNITS + gcol] = __float2half_rn(r * hreg);
                zreg = z;
            }
        }
        grid_barrier(++bseq * GRID);

        // =================== Phase B: mh_partial = rh @ Wh (half-K) ==========
        {
            const char* src = (const char*)g_rhx;

            float ah0[4], ah1[4];
#pragma unroll
            for (int c = 0; c < 4; c++) { ah0[c] = 0.f; ah1[c] = 0.f; }

#pragma unroll
            for (int cchunk = 0; cchunk < 2; cchunk++) {
#pragma unroll
                for (int i = 0; i < 4; i++)
                    cp_async16(st_s[i] + cchunk * (CHUNKU * 4),
                               src + ((size_t)(st_r[i] * UNITS + koff)) * 2
                                   + cchunk * 512 + st_c[i] * 16);
                CP_COMMIT();
            }

            CP_WAIT1();
            __syncthreads();
#pragma unroll
            for (int kc = 0; kc < 4; kc++) {
                const int kw = kc * 32 + fcol;
                const uint32_t* hb = &smu[SM_STG];
                uint32_t a0 = hb[(r0    ) * 132 + kw];
                uint32_t a1 = hb[(r0 + 8) * 132 + kw];
                uint32_t a2 = hb[(r0    ) * 132 + kw + 4];
                uint32_t a3 = hb[(r0 + 8) * 132 + kw + 4];
                MMA_F16(ah0[0], ah0[1], ah0[2], ah0[3], a0, a1, a2, a3, wsh0[kw], wsh0[kw + 4]);
                MMA_F16(ah1[0], ah1[1], ah1[2], ah1[3], a0, a1, a2, a3, wsh1[kw], wsh1[kw + 4]);
            }
            CP_WAIT0();
            __syncthreads();
#pragma unroll
            for (int kc = 0; kc < 4; kc++) {
                const int kwl = kc * 32 + fcol;
                const int kw  = 128 + kwl;
                const uint32_t* hb = &smu[SM_STG + CHUNKU];
                uint32_t a0 = hb[(r0    ) * 132 + kwl];
                uint32_t a1 = hb[(r0 + 8) * 132 + kwl];
                uint32_t a2 = hb[(r0    ) * 132 + kwl + 4];
                uint32_t a3 = hb[(r0 + 8) * 132 + kwl + 4];
                MMA_F16(ah0[0], ah0[1], ah0[2], ah0[3], a0, a1, a2, a3, wsh0[kw], wsh0[kw + 4]);
                MMA_F16(ah1[0], ah1[1], ah1[2], ah1[3], a0, a1, a2, a3, wsh1[kw], wsh1[kw + 4]);
            }

            __syncthreads();

            // warp partials: C[16x16], row stride 17
            float* pw = pacc + wid * 272;
            pw[(gID    ) * 17 + 0 + 2 * tig    ] = ah0[0];
            pw[(gID    ) * 17 + 0 + 2 * tig + 1] = ah0[1];
            pw[(gID + 8) * 17 + 0 + 2 * tig    ] = ah0[2];
            pw[(gID + 8) * 17 + 0 + 2 * tig + 1] = ah0[3];
            pw[(gID    ) * 17 + 8 + 2 * tig    ] = ah1[0];
            pw[(gID    ) * 17 + 8 + 2 * tig + 1] = ah1[1];
            pw[(gID + 8) * 17 + 8 + 2 * tig    ] = ah1[2];
            pw[(gID + 8) * 17 + 8 + 2 * tig + 1] = ah1[3];
            __syncthreads();

            // reduce 4 k-slices -> redB[64][17]
            {
                float s0 = 0.f, s1 = 0.f;
#pragma unroll
                for (int s = 0; s < 4; s++) {
                    const float* p = pacc + (s * 4 + rmgr) * 272 + rlr * 17 + rc2;
                    s0 += p[0]; s1 += p[1];
                }
                float* rd = redB + rrow * 17 + rc2;
                rd[0] = s0; rd[1] = s1;
            }
            CLUSTER_SYNC();

            // h update: own + peer partial
            {
                const uint32_t hlocA = s2u(&redB[grow * 17 + lcol]);
                float mp = sm[SM_REDB + grow * 17 + lcol] + dsmem_ld(hlocA, peer);
                const float a = xh + mp;
                const float hh = 1.f - 2.f / (1.f + __expf(2.f * a));  // tanh(a)
                const float hn = zreg * hreg + (1.f - zreg) * hh;
                hreg = hn;
                g_hx[grow * UNITS + gcol] = __float2half_rn(hn);
                out[((size_t)(grow * TLEN + t)) * UNITS + gcol] = hn;
                if (t == TLEN - 1)
                    out[(size_t)BATCH * TLEN * UNITS + (size_t)grow * UNITS + gcol] = hn;
            }
        }
        grid_barrier(++bseq * GRID);
    }
}

// ---------------------------------------------------------------------------
extern "C" void kernel_launch(void* const* d_in, const int* in_sizes, int n_in,
                              void* d_out, int out_size)
{
    const int*   x      = (const int*)d_in[0];
    const float* hidden = (const float*)d_in[1];
    const float* emb    = (const float*)d_in[2];
    const float* kern   = (const float*)d_in[3];
    const float* rk     = (const float*)d_in[4];
    const float* bias   = (const float*)d_in[5];
    float* out = (float*)d_out;

    static bool attr_set = false;
    if (!attr_set) {
        cudaFuncSetAttribute(gru_scan, cudaFuncAttributeMaxDynamicSharedMemorySize,
                             SMEM_FLOATS * sizeof(float));
        attr_set = true;
    }

    // Node 1: projection GEMM (tf32, cp.async pipelined, occ=2) + barrier reset
    xproj_tf32<<<dim3(N3 / 128, (BATCH * TLEN) / 128), 256>>>(x, emb, kern, bias);

    // Node 2: persistent GRU scan (cluster-2 split-K, fp16, 2-chunk pipeline)
    gru_scan<<<GRID, TPB, SMEM_FLOATS * sizeof(float)>>>(hidden, rk, out);
}